// round 11
// baseline (speedup 1.0000x reference)
#include <cuda_runtime.h>
#include <cstdint>

#define HW 16384
#define NB 2
#define CSTR 320

// ---------------- scratch (device globals; no allocations allowed) ----------
// NHWC concat buffer, per pixel 320 ch: [xl(0) | xr(64) | xd(128) | xl2(192) | xr2(256)]
__device__ __align__(16) float g_nhwc[NB*HW*CSTR];
__device__ __align__(16) float g_offb[NB*HW*32];   // offset conv out, NHWC32
__device__ __align__(16) float g_x0  [NB*HW*64];   // NHWC64
__device__ __align__(16) float g_tmp [NB*HW*64];
__device__ __align__(16) float g_x1  [NB*HW*64];
__device__ __align__(16) float g_dlw [73728];      // deform weights, mma frag order hi+lo
__device__ __align__(16) float g_drw [73728];
__device__ __align__(16) float g_wp  [737280];     // mma-frag-order conv weights (hi+lo)

// float offsets into g_wp
#define WP_OFFL 0
#define WP_OFFR 110592
#define WP_CV   221184
#define WP_RB11 442368
#define WP_RB12 516096
#define WP_RB21 589824
#define WP_RB22 663552

// ---------------- helpers ----------------------------------------------------
__device__ __forceinline__ float tf32r(float x){
    uint32_t u; asm("cvt.rna.tf32.f32 %0, %1;" : "=r"(u) : "f"(x));
    return __uint_as_float(u);
}
__device__ __forceinline__ void mma1688(float* d, const float* a, const float2 b){
    asm volatile(
      "mma.sync.aligned.m16n8k8.row.col.f32.tf32.tf32.f32 "
      "{%0,%1,%2,%3}, {%4,%5,%6,%7}, {%8,%9}, {%0,%1,%2,%3};"
      : "+f"(d[0]), "+f"(d[1]), "+f"(d[2]), "+f"(d[3])
      : "r"(__float_as_uint(a[0])), "r"(__float_as_uint(a[1])),
        "r"(__float_as_uint(a[2])), "r"(__float_as_uint(a[3])),
        "r"(__float_as_uint(b.x)),  "r"(__float_as_uint(b.y)));
}

// ---------------- device bodies for prep tasks -------------------------------
// Deform weight -> mma fragment order (hi+lo). One thread per weight value.
// kc ordering matches s_samp: kc = tap*64 + ch.
__device__ __forceinline__ void body_prep_dw(const float* __restrict__ w,
                                             float* __restrict__ dwp, int i)
{
    int f2 = i >> 1; int b = i & 1;
    int lane = f2 & 31; int u = f2 >> 5;
    int ws = u & 7; int ks = u >> 3;
    int g = lane >> 2, tig = lane & 3;
    int kc = ks*8 + tig + b*4;
    int oc = ws*8 + g;
    float v = w[(oc*64 + (kc & 63))*9 + (kc >> 6)];
    float hi = tf32r(v);
    float lo = tf32r(v - hi);
    int fi = ((ks*8 + ws)*32 + lane)*2 + b;
    dwp[fi]         = hi;
    dwp[36864 + fi] = lo;
}

// fragment-order (hi+lo) conv weight pack; see k_convMMA for layout
__device__ __forceinline__ void body_prep_wtc(const float* __restrict__ w,
                                              float* __restrict__ wp,
                                              int Cin, int Cout, int NP, int i)
{
    int per = NP*64;
    int q  = i / per;
    int r  = i - q*per;
    int b   = r & 1;
    int tq  = r >> 1;
    int lane = tq & 31;
    int u    = tq >> 5;
    int ntg  = u % (NP >> 3);
    int ks   = u / (NP >> 3);
    int oc = ntg*8 + (lane >> 2);
    int ch = ks*8 + (lane & 3) + b*4;
    int nic = Cin >> 6;
    int j  = q / nic;
    int ib = q - j*nic;
    float v = (oc < Cout) ? w[((size_t)oc*Cin + ib*64 + ch)*9 + j] : 0.f;
    float hi = tf32r(v);
    float lo = tf32r(v - hi);
    size_t base = (size_t)q * 2 * per;
    wp[base + r]       = hi;
    wp[base + per + r] = lo;
}

// ---------------- one merged prep kernel (all independent re-layouts) --------
__global__ void __launch_bounds__(256)
k_prep_all(const float* __restrict__ xl, const float* __restrict__ xr,
           float* __restrict__ nhwc,
           const float* __restrict__ dl_w, const float* __restrict__ dr_w,
           float* __restrict__ dlw, float* __restrict__ drw,
           const float* __restrict__ offl_w, const float* __restrict__ offr_w,
           const float* __restrict__ cv_w,
           const float* __restrict__ r11, const float* __restrict__ r12,
           const float* __restrict__ r21, const float* __restrict__ r22,
           float* __restrict__ wp)
{
    __shared__ float tile[32][33];
    int b = blockIdx.x, t = threadIdx.x;
    if (b < 4096){
        const float* in = (b < 2048) ? xl : xr;
        int coloff = (b < 2048) ? 0 : 64;
        int bb = b & 2047;
        int n  = bb >> 10;
        int c0 = ((bb >> 9) & 1) * 32;
        int p0 = (bb & 511) * 32;
        int tx = t & 31, ty = t >> 5;
        const float* src = in + (size_t)n*64*HW;
        float* dst = nhwc + (size_t)n*HW*CSTR;
        #pragma unroll
        for (int i = 0; i < 32; i += 8)
            tile[ty+i][tx] = src[(c0+ty+i)*HW + p0 + tx];
        __syncthreads();
        #pragma unroll
        for (int i = 0; i < 32; i += 8)
            dst[(size_t)(p0+ty+i)*CSTR + coloff + c0 + tx] = tile[tx][ty+i];
    } else if (b < 4240){
        body_prep_dw(dl_w, dlw, (b-4096)*256 + t);
    } else if (b < 4384){
        body_prep_dw(dr_w, drw, (b-4240)*256 + t);
    } else if (b < 4600){
        body_prep_wtc(offl_w, wp + WP_OFFL, 192, 27, 32, (b-4384)*256 + t);
    } else if (b < 4816){
        body_prep_wtc(offr_w, wp + WP_OFFR, 192, 27, 32, (b-4600)*256 + t);
    } else if (b < 5248){
        body_prep_wtc(cv_w,   wp + WP_CV,   192, 64, 64, (b-4816)*256 + t);
    } else if (b < 5392){
        body_prep_wtc(r11,    wp + WP_RB11,  64, 64, 64, (b-5248)*256 + t);
    } else if (b < 5536){
        body_prep_wtc(r12,    wp + WP_RB12,  64, 64, 64, (b-5392)*256 + t);
    } else if (b < 5680){
        body_prep_wtc(r21,    wp + WP_RB21,  64, 64, 64, (b-5536)*256 + t);
    } else {
        body_prep_wtc(r22,    wp + WP_RB22,  64, 64, 64, (b-5680)*256 + t);
    }
}

// ---------------- upsample(2x nearest) + 2x2 conv + pad -> NHWC cols 128-191
__global__ void k_upconv(const float* __restrict__ xd, const float* __restrict__ w,
                         const float* __restrict__ bias, float* __restrict__ out)
{
    __shared__ float4 s_w4[2048];        // 16 oc x 128 ic x 4 taps
    __shared__ float  s_in[9*18];
    int n      = blockIdx.z;
    int ocBase = blockIdx.y * 16;
    int tx0 = (blockIdx.x & 3) * 32;
    int ty0 = (blockIdx.x >> 2) * 16;
    int t  = threadIdx.x;
    int lx = t & 31, ly = t >> 5;

    float* s_w = (float*)s_w4;
    for (int i = t; i < 8192; i += 256) s_w[i] = w[ocBase*512 + i];
    __syncthreads();

    const float* src = xd + (size_t)n*128*4096;
    float accA[16], accB[16];
    #pragma unroll
    for (int oc = 0; oc < 16; oc++){ accA[oc] = 0.f; accB[oc] = 0.f; }

    int X  = tx0 + lx;
    int YA = ty0 + ly, YB = ty0 + ly + 8;
    bool doA = (YA < 127) && (X < 127);
    bool doB = (YB < 127) && (X < 127);
    int x0r = lx >> 1,      x1r = (lx+1) >> 1;
    int yA0 = ly >> 1,      yA1 = (ly+1) >> 1;
    int yB0 = (ly+8) >> 1,  yB1 = (ly+9) >> 1;

    for (int ic = 0; ic < 128; ic++){
        const float* p = src + ic*4096;
        if (t < 162){
            int r = t/18, c = t - r*18;
            int gy = (ty0>>1) + r, gx = (tx0>>1) + c;
            s_in[t] = (gy < 64 && gx < 64) ? p[gy*64 + gx] : 0.f;
        }
        __syncthreads();
        if (doA){
            float v00 = s_in[yA0*18+x0r], v01 = s_in[yA0*18+x1r];
            float v10 = s_in[yA1*18+x0r], v11 = s_in[yA1*18+x1r];
            #pragma unroll
            for (int oc = 0; oc < 16; oc++){
                float4 wv = s_w4[oc*128 + ic];
                accA[oc] += wv.x*v00 + wv.y*v01 + wv.z*v10 + wv.w*v11;
            }
        }
        if (doB){
            float v00 = s_in[yB0*18+x0r], v01 = s_in[yB0*18+x1r];
            float v10 = s_in[yB1*18+x0r], v11 = s_in[yB1*18+x1r];
            #pragma unroll
            for (int oc = 0; oc < 16; oc++){
                float4 wv = s_w4[oc*128 + ic];
                accB[oc] += wv.x*v00 + wv.y*v01 + wv.z*v10 + wv.w*v11;
            }
        }
        __syncthreads();
    }
    float* ob = out + (size_t)n*HW*CSTR;
    #pragma unroll
    for (int oc = 0; oc < 16; oc++){
        int o = ocBase + oc;
        float bv = bias[o];
        ob[(size_t)(YA*128+X)*CSTR + 128 + o] = doA ? (accA[oc] + bv) : 0.f;
        ob[(size_t)(YB*128+X)*CSTR + 128 + o] = doB ? (accB[oc] + bv) : 0.f;
    }
}

// ---------------- mma.sync TF32 implicit-GEMM 3x3 conv ----------------------
template<int NP>
__global__ void __launch_bounds__(256)
k_convMMA(const float* __restrict__ in, int inStride,
          int co0, int co1, int co2, int nicblk,
          const float* __restrict__ wp,
          const float* __restrict__ bias,
          float* __restrict__ out, int outStride, int outCol, int outNCHW, int Cout,
          const float* __restrict__ res, int relu)
{
    constexpr int NT  = NP/16;       // n tiles per warp
    constexpr int per = NP*64;       // floats per B half-chunk
    constexpr int A_FLOAT2 = 8*130*4;        // 4160 float2 per buffer
    extern __shared__ char smem[];
    float2* sAh = (float2*)smem;
    float2* sAl = sAh + A_FLOAT2;

    int t = threadIdx.x, lane = t & 31, wrp = t >> 5;
    int mw = wrp & 3, nw = wrp >> 2;
    int g = lane >> 2, tig = lane & 3;
    int y = blockIdx.x, n = blockIdx.z;
    const float* inN = in + (size_t)n*HW*inStride;
    int cos[3] = {co0, co1, co2};

    float d[2][NT][4];
    #pragma unroll
    for (int mt = 0; mt < 2; mt++)
        #pragma unroll
        for (int nt = 0; nt < NT; nt++)
            #pragma unroll
            for (int k = 0; k < 4; k++) d[mt][nt][k] = 0.f;

    for (int ib = 0; ib < nicblk; ib++){
        int co = cos[ib];
        for (int dy = 0; dy < 3; dy++){
            int ys = y + dy - 1;
            bool yv = (unsigned)ys < 128u;
            __syncthreads();                    // prior readers of sA done
            // stage A: 130 px x 8 ks-groups, hi/lo split + pair packing
            for (int i = t; i < 1040; i += 256){
                int ks = i / 130, s = i - ks*130;
                int x = s - 1;
                float4 v0 = make_float4(0.f,0.f,0.f,0.f);
                float4 v1 = make_float4(0.f,0.f,0.f,0.f);
                if (yv && (unsigned)x < 128u){
                    const float* p = inN + (size_t)(ys*128 + x)*inStride + co + ks*8;
                    v0 = *(const float4*)p;
                    v1 = *(const float4*)(p + 4);
                }
                int base = (ks*130 + s)*4;
                float2 h, l;
                h.x = tf32r(v0.x); l.x = tf32r(v0.x - h.x);
                h.y = tf32r(v1.x); l.y = tf32r(v1.x - h.y);
                sAh[base+0] = h; sAl[base+0] = l;
                h.x = tf32r(v0.y); l.x = tf32r(v0.y - h.x);
                h.y = tf32r(v1.y); l.y = tf32r(v1.y - h.y);
                sAh[base+1] = h; sAl[base+1] = l;
                h.x = tf32r(v0.z); l.x = tf32r(v0.z - h.x);
                h.y = tf32r(v1.z); l.y = tf32r(v1.z - h.y);
                sAh[base+2] = h; sAl[base+2] = l;
                h.x = tf32r(v0.w); l.x = tf32r(v0.w - h.x);
                h.y = tf32r(v1.w); l.y = tf32r(v1.w - h.y);
                sAh[base+3] = h; sAl[base+3] = l;
            }
            __syncthreads();                    // sA ready
            for (int dx = 0; dx < 3; dx++){
                int q = (dy*3 + dx)*nicblk + ib;
                const float2* wB = (const float2*)(wp + (size_t)q*2*per);
                int s0 = mw*32 + g + dx;
                #pragma unroll
                for (int ks = 0; ks < 8; ks++){
                    float ah[2][4], al[2][4];
                    #pragma unroll
                    for (int mt = 0; mt < 2; mt++){
                        int bi = (ks*130 + s0 + mt*16)*4 + tig;
                        float2 hg  = sAh[bi];
                        float2 hg8 = sAh[bi + 32];
                        float2 lg  = sAl[bi];
                        float2 lg8 = sAl[bi + 32];
                        ah[mt][0] = hg.x;  ah[mt][1] = hg8.x;
                        ah[mt][2] = hg.y;  ah[mt][3] = hg8.y;
                        al[mt][0] = lg.x;  al[mt][1] = lg8.x;
                        al[mt][2] = lg.y;  al[mt][3] = lg8.y;
                    }
                    float2 bh[NT], bl[NT];
                    #pragma unroll
                    for (int nt = 0; nt < NT; nt++){
                        int idx = (ks*(NP>>3) + nw*NT + nt)*32 + lane;
                        bh[nt] = __ldg(wB + idx);
                        bl[nt] = __ldg(wB + idx + per/2);
                    }
                    #pragma unroll
                    for (int mt = 0; mt < 2; mt++)
                        #pragma unroll
                        for (int nt = 0; nt < NT; nt++){
                            mma1688(d[mt][nt], ah[mt], bh[nt]);
                            mma1688(d[mt][nt], ah[mt], bl[nt]);
                            mma1688(d[mt][nt], al[mt], bh[nt]);
                        }
                }
            }
        }
    }

    // ---- epilogue ----
    #pragma unroll
    for (int mt = 0; mt < 2; mt++){
        int p0 = y*128 + mw*32 + mt*16 + g;
        int p1 = p0 + 8;
        #pragma unroll
        for (int nt = 0; nt < NT; nt++){
            int oc0 = nw*(NP/2) + nt*8 + 2*tig;
            float v00 = d[mt][nt][0], v01 = d[mt][nt][1];
            float v10 = d[mt][nt][2], v11 = d[mt][nt][3];
            float b0v = (oc0   < Cout) ? bias[oc0]   : 0.f;
            float b1v = (oc0+1 < Cout) ? bias[oc0+1] : 0.f;
            v00 += b0v; v01 += b1v; v10 += b0v; v11 += b1v;
            if (res){
                v00 += res[((size_t)n*HW + p0)*64 + oc0];
                v01 += res[((size_t)n*HW + p0)*64 + oc0 + 1];
                v10 += res[((size_t)n*HW + p1)*64 + oc0];
                v11 += res[((size_t)n*HW + p1)*64 + oc0 + 1];
            }
            if (relu){
                v00 = fmaxf(v00, 0.f); v01 = fmaxf(v01, 0.f);
                v10 = fmaxf(v10, 0.f); v11 = fmaxf(v11, 0.f);
            }
            if (outNCHW){
                if (oc0 < Cout){
                    out[((size_t)n*Cout + oc0)*HW + p0] = v00;
                    out[((size_t)n*Cout + oc0)*HW + p1] = v10;
                }
                if (oc0 + 1 < Cout){
                    out[((size_t)n*Cout + oc0+1)*HW + p0] = v01;
                    out[((size_t)n*Cout + oc0+1)*HW + p1] = v11;
                }
            } else {
                float* o0 = out + ((size_t)n*HW + p0)*outStride + outCol;
                float* o1 = out + ((size_t)n*HW + p1)*outStride + outCol;
                if (oc0 + 1 < Cout){
                    *(float2*)(o0 + oc0) = make_float2(v00, v01);
                    *(float2*)(o1 + oc0) = make_float2(v10, v11);
                } else if (oc0 < Cout){
                    o0[oc0] = v00; o1[oc0] = v10;
                }
            }
        }
    }
}

// ---------------- modulated deformable 3x3 conv (mma GEMM) -------------------
// Phase A additionally precomputes, per (px,k): four gather base offsets in
// float2 units (-1 = OOB, folding both bounds checks into a sign test) and
// four mask-premultiplied bilinear weights. The per-lane gather loop is then
// broadcast-LDS + predicated float2 loads + FMA only (no per-lane address ALU).
#define PXS 580
__global__ void k_deform(const float* __restrict__ nhwc, int xco,
                         const float* __restrict__ off,
                         const float* __restrict__ dwp, const float* __restrict__ bias,
                         float* __restrict__ out, int oco)
{
    extern __shared__ char smem[];
    float* smf = (float*)smem;
    float* s_samp = smf;                  // 16 * 580 floats
    float* s_w00  = smf + 16*PXS;
    float* s_w01  = s_w00 + 144;
    float* s_w10  = s_w01 + 144;
    float* s_w11  = s_w10 + 144;
    int*   s_o00  = (int*)(s_w11 + 144);
    int*   s_o01  = s_o00 + 144;
    int*   s_o10  = s_o01 + 144;
    int*   s_o11  = s_o10 + 144;

    int n  = blockIdx.z;
    int y0 = blockIdx.y * 2;
    int x0 = blockIdx.x * 8;
    int t  = threadIdx.x;

    if (t < 144){
        int p = t / 9, k = t - p*9;
        int yy = y0 + (p >> 3), xx = x0 + (p & 7);
        const float* ob = off + ((size_t)n*HW + yy*128 + xx)*32;
        float dyv = ob[2*k];
        float dxv = ob[2*k+1];
        float mv  = 1.f / (1.f + __expf(-ob[18+k]));
        float py = dyv + (float)(k/3) - 1.f + (float)yy;
        float px = dxv + (float)(k%3) - 1.f + (float)xx;
        float fy = floorf(py), fx = floorf(px);
        int iy0 = (int)fy, ix0 = (int)fx;
        float wy = py - fy, wx = px - fx;
        int iy1 = iy0 + 1, ix1 = ix0 + 1;
        bool y0v = (unsigned)iy0 < 128u, y1v = (unsigned)iy1 < 128u;
        bool x0v = (unsigned)ix0 < 128u, x1v = (unsigned)ix1 < 128u;
        s_o00[t] = (y0v && x0v) ? (iy0*128 + ix0)*160 : -1;
        s_o01[t] = (y0v && x1v) ? (iy0*128 + ix1)*160 : -1;
        s_o10[t] = (y1v && x0v) ? (iy1*128 + ix0)*160 : -1;
        s_o11[t] = (y1v && x1v) ? (iy1*128 + ix1)*160 : -1;
        s_w00[t] = mv*(1.f-wy)*(1.f-wx);
        s_w01[t] = mv*(1.f-wy)*wx;
        s_w10[t] = mv*wy*(1.f-wx);
        s_w11[t] = mv*wy*wx;
    }
    __syncthreads();

    int lane = t & 31, wrp = t >> 5;
    int g = lane >> 2, tig = lane & 3;
    const float2* xb = (const float2*)(nhwc + (size_t)n*HW*CSTR + xco);  // idx: pix*160 + lane
    float2* s_samp2 = (float2*)s_samp;    // px stride PXS/2 = 290 float2
    for (int pp = wrp; pp < 16; pp += 8){
        #pragma unroll
        for (int k = 0; k < 9; k++){
            int pk = pp*9 + k;
            int o00 = s_o00[pk], o01 = s_o01[pk], o10 = s_o10[pk], o11 = s_o11[pk];
            float w00 = s_w00[pk], w01 = s_w01[pk], w10 = s_w10[pk], w11 = s_w11[pk];
            float ax = 0.f, ay = 0.f;
            if (o00 >= 0){ float2 v = xb[o00 + lane]; ax = fmaf(w00, v.x, ax); ay = fmaf(w00, v.y, ay); }
            if (o01 >= 0){ float2 v = xb[o01 + lane]; ax = fmaf(w01, v.x, ax); ay = fmaf(w01, v.y, ay); }
            if (o10 >= 0){ float2 v = xb[o10 + lane]; ax = fmaf(w10, v.x, ax); ay = fmaf(w10, v.y, ay); }
            if (o11 >= 0){ float2 v = xb[o11 + lane]; ax = fmaf(w11, v.x, ax); ay = fmaf(w11, v.y, ay); }
            s_samp2[pp*290 + k*32 + lane] = make_float2(ax, ay);
        }
    }
    __syncthreads();

    // GEMM 16x64x576: warp wrp -> oc slice [8*wrp, 8*wrp+8)
    float d[4] = {0.f, 0.f, 0.f, 0.f};
    const float2* wb = (const float2*)dwp;           // hi: 18432 float2, lo: +18432
    const float* pg  = s_samp + g*PXS;
    const float* pg8 = s_samp + (g+8)*PXS;
    #pragma unroll 4
    for (int ks = 0; ks < 72; ks++){
        int c0 = ks*8 + tig;
        float a0 = pg [c0],     a1 = pg8[c0];
        float a2 = pg [c0 + 4], a3 = pg8[c0 + 4];
        float ah[4], al[4];
        ah[0] = tf32r(a0); al[0] = tf32r(a0 - ah[0]);
        ah[1] = tf32r(a1); al[1] = tf32r(a1 - ah[1]);
        ah[2] = tf32r(a2); al[2] = tf32r(a2 - ah[2]);
        ah[3] = tf32r(a3); al[3] = tf32r(a3 - ah[3]);
        int bidx = (ks*8 + wrp)*32 + lane;
        float2 bh = __ldg(wb + bidx);
        float2 bl = __ldg(wb + 18432 + bidx);
        mma1688(d, ah, bh);
        mma1688(d, ah, bl);
        mma1688(d, al, bh);
    }

    // epilogue: d = [(px g, oc 2tig), (g, 2tig+1), (g+8, 2tig), (g+8, 2tig+1)]
    int oc0 = 8*wrp + 2*tig;
    float b0 = bias[oc0], b1 = bias[oc0+1];
    {
        int px = g;
        int yy = y0 + (px >> 3), xx = x0 + (px & 7);
        float* op = out + ((size_t)n*HW + yy*128 + xx)*CSTR + oco + oc0;
        *(float2*)op = make_float2(d[0] + b0, d[1] + b1);
    }
    {
        int px = g + 8;
        int yy = y0 + (px >> 3), xx = x0 + (px & 7);
        float* op = out + ((size_t)n*HW + yy*128 + xx)*CSTR + oco + oc0;
        *(float2*)op = make_float2(d[2] + b0, d[3] + b1);
    }
}

// ---------------------------------------------------------------------------
extern "C" void kernel_launch(void* const* d_in, const int* in_sizes, int n_in,
                              void* d_out, int out_size)
{
    const float* xd     = (const float*)d_in[0];
    const float* xl     = (const float*)d_in[1];
    const float* xr     = (const float*)d_in[2];
    const float* up_w   = (const float*)d_in[3];
    const float* up_b   = (const float*)d_in[4];
    const float* offl_w = (const float*)d_in[5];
    const float* offl_b = (const float*)d_in[6];
    const float* dl_w   = (const float*)d_in[7];
    const float* dl_b   = (const float*)d_in[8];
    const float* offr_w = (const float*)d_in[9];
    const float* offr_b = (const float*)d_in[10];
    const float* dr_w   = (const float*)d_in[11];
    const float* dr_b   = (const float*)d_in[12];
    const float* cv_w   = (const float*)d_in[13];
    const float* cv_b   = (const float*)d_in[14];

    const float *rb1_w1, *rb1_b1, *rb1_w2, *rb1_b2;
    const float *rb2_w1, *rb2_b1, *rb2_w2, *rb2_b2;
    if (in_sizes[16] == 64){
        rb1_w1 = (const float*)d_in[15]; rb1_b1 = (const float*)d_in[16];
        rb1_w2 = (const float*)d_in[17]; rb1_b2 = (const float*)d_in[18];
        rb2_w1 = (const float*)d_in[19]; rb2_b1 = (const float*)d_in[20];
        rb2_w2 = (const float*)d_in[21]; rb2_b2 = (const float*)d_in[22];
    } else {
        rb1_w1 = (const float*)d_in[15]; rb1_w2 = (const float*)d_in[16];
        rb2_w1 = (const float*)d_in[17]; rb2_w2 = (const float*)d_in[18];
        rb1_b1 = (const float*)d_in[19]; rb1_b2 = (const float*)d_in[20];
        rb2_b1 = (const float*)d_in[21]; rb2_b2 = (const float*)d_in[22];
    }

    float *p_nhwc, *p_off, *p_x0, *p_tmp, *p_x1, *p_dlw, *p_drw, *p_wp;
    cudaGetSymbolAddress((void**)&p_nhwc, g_nhwc);
    cudaGetSymbolAddress((void**)&p_off,  g_offb);
    cudaGetSymbolAddress((void**)&p_x0,   g_x0);
    cudaGetSymbolAddress((void**)&p_tmp,  g_tmp);
    cudaGetSymbolAddress((void**)&p_x1,   g_x1);
    cudaGetSymbolAddress((void**)&p_dlw,  g_dlw);
    cudaGetSymbolAddress((void**)&p_drw,  g_drw);
    cudaGetSymbolAddress((void**)&p_wp,   g_wp);

    // conv smem: A hi/lo only = 2*33280 = 66560 (3 blocks/SM)
    const int SMC = 66560;
    cudaFuncSetAttribute(k_convMMA<64>, cudaFuncAttributeMaxDynamicSharedMemorySize, SMC);
    cudaFuncSetAttribute(k_convMMA<32>, cudaFuncAttributeMaxDynamicSharedMemorySize, SMC);
    const int SMD = (16*PXS + 8*144)*4 + 64;   // ~41.8KB

    // 1: all independent prep work in one launch
    k_prep_all<<<5824, 256>>>(xl, xr, p_nhwc, dl_w, dr_w, p_dlw, p_drw,
                              offl_w, offr_w, cv_w, rb1_w1, rb1_w2, rb2_w1, rb2_w2, p_wp);
    // 2: upsample-conv -> NHWC cols 128-191
    k_upconv<<<dim3(32, 4, 2), 256>>>(xd, up_w, up_b, p_nhwc);

    dim3 cg(128, 1, 2);
    // 3: left offset conv (192->27) on [xl|xr|xd]
    k_convMMA<32><<<cg, 256, SMC>>>(p_nhwc, CSTR, 0, 64, 128, 3, p_wp + WP_OFFL,
                                    offl_b, p_off, 32, 0, 0, 27, nullptr, 0);
    // 4: deform xl -> cols 192
    k_deform<<<dim3(16, 64, 2), 256, SMD>>>(p_nhwc, 0,   p_off, p_dlw, dl_b, p_nhwc, 192);
    // 5: right offset conv on [xl2|xr|xd]
    k_convMMA<32><<<cg, 256, SMC>>>(p_nhwc, CSTR, 192, 64, 128, 3, p_wp + WP_OFFR,
                                    offr_b, p_off, 32, 0, 0, 27, nullptr, 0);
    // 6: deform xr -> cols 256
    k_deform<<<dim3(16, 64, 2), 256, SMD>>>(p_nhwc, 64,  p_off, p_drw, dr_b, p_nhwc, 256);
    // 7: fuse conv (192->64) + ReLU on [xl2|xr2|xd] -> x0 (NHWC64)
    k_convMMA<64><<<cg, 256, SMC>>>(p_nhwc, CSTR, 192, 256, 128, 3, p_wp + WP_CV,
                                    cv_b, p_x0, 64, 0, 0, 64, nullptr, 1);
    // 8-9: residual block 1
    k_convMMA<64><<<cg, 256, SMC>>>(p_x0,  64, 0, 0, 0, 1, p_wp + WP_RB11,
                                    rb1_b1, p_tmp, 64, 0, 0, 64, nullptr, 1);
    k_convMMA<64><<<cg, 256, SMC>>>(p_tmp, 64, 0, 0, 0, 1, p_wp + WP_RB12,
                                    rb1_b2, p_x1, 64, 0, 0, 64, p_x0, 0);
    // 10-11: residual block 2 (final conv writes NCHW straight to d_out)
    k_convMMA<64><<<cg, 256, SMC>>>(p_x1,  64, 0, 0, 0, 1, p_wp + WP_RB21,
                                    rb2_b1, p_tmp, 64, 0, 0, 64, nullptr, 1);
    k_convMMA<64><<<cg, 256, SMC>>>(p_tmp, 64, 0, 0, 0, 1, p_wp + WP_RB22,
                                    rb2_b2, (float*)d_out, 64, 0, 1, 64, p_x1, 0);
}

// round 12
// speedup vs baseline: 1.0840x; 1.0840x over previous
#include <cuda_runtime.h>
#include <cstdint>

#define HW 16384
#define NB 2
#define CSTR 320

// ---------------- scratch (device globals; no allocations allowed) ----------
// NHWC concat buffer, per pixel 320 ch: [xl(0) | xr(64) | xd(128) | xl2(192) | xr2(256)]
__device__ __align__(16) float g_nhwc[NB*HW*CSTR];
__device__ __align__(16) float g_offb[NB*HW*32];   // offset conv out, NHWC32
__device__ __align__(16) float g_x0  [NB*HW*64];   // NHWC64
__device__ __align__(16) float g_tmp [NB*HW*64];
__device__ __align__(16) float g_x1  [NB*HW*64];
__device__ __align__(16) float g_dlw [73728];      // deform weights, mma frag order hi+lo
__device__ __align__(16) float g_drw [73728];
__device__ __align__(16) float g_wp  [737280];     // mma-frag-order conv weights (hi+lo)

// float offsets into g_wp
#define WP_OFFL 0
#define WP_OFFR 110592
#define WP_CV   221184
#define WP_RB11 442368
#define WP_RB12 516096
#define WP_RB21 589824
#define WP_RB22 663552

// ---------------- helpers ----------------------------------------------------
__device__ __forceinline__ float tf32r(float x){
    uint32_t u; asm("cvt.rna.tf32.f32 %0, %1;" : "=r"(u) : "f"(x));
    return __uint_as_float(u);
}
__device__ __forceinline__ void mma1688(float* d, const float* a, const float2 b){
    asm volatile(
      "mma.sync.aligned.m16n8k8.row.col.f32.tf32.tf32.f32 "
      "{%0,%1,%2,%3}, {%4,%5,%6,%7}, {%8,%9}, {%0,%1,%2,%3};"
      : "+f"(d[0]), "+f"(d[1]), "+f"(d[2]), "+f"(d[3])
      : "r"(__float_as_uint(a[0])), "r"(__float_as_uint(a[1])),
        "r"(__float_as_uint(a[2])), "r"(__float_as_uint(a[3])),
        "r"(__float_as_uint(b.x)),  "r"(__float_as_uint(b.y)));
}

// ---------------- dummy kernel (shifts ncu -s5 -c1 capture onto a conv) -----
__global__ void k_nop(){}

// ---------------- device bodies for prep tasks -------------------------------
// Deform weight -> mma fragment order (hi+lo). One thread per weight value.
__device__ __forceinline__ void body_prep_dw(const float* __restrict__ w,
                                             float* __restrict__ dwp, int i)
{
    int f2 = i >> 1; int b = i & 1;
    int lane = f2 & 31; int u = f2 >> 5;
    int ws = u & 7; int ks = u >> 3;
    int g = lane >> 2, tig = lane & 3;
    int kc = ks*8 + tig + b*4;
    int oc = ws*8 + g;
    float v = w[(oc*64 + (kc & 63))*9 + (kc >> 6)];
    float hi = tf32r(v);
    float lo = tf32r(v - hi);
    int fi = ((ks*8 + ws)*32 + lane)*2 + b;
    dwp[fi]         = hi;
    dwp[36864 + fi] = lo;
}

// Conv weight pack, float4-vectorized fragment order (hi+lo).
// Per chunk q: hi half then lo half, each per=NP*64 floats.
// float index r in chunk half: e=r&3, u2=r>>2, lane=u2&31, v=u2>>5,
//   nwh = v % (NP>>4), ks = v / (NP>>4),
//   nt  = nwh*2 + (e>>1), oc = nt*8 + (lane>>2), ch = ks*8 + (lane&3) + (e&1)*4.
__device__ __forceinline__ void body_prep_wtc(const float* __restrict__ w,
                                              float* __restrict__ wp,
                                              int Cin, int Cout, int NP, int i)
{
    int per = NP*64;
    int q  = i / per;
    int r  = i - q*per;
    int e  = r & 3;
    int u2 = r >> 2;
    int lane = u2 & 31;
    int v  = u2 >> 5;
    int npq = NP >> 4;
    int nwh = v % npq;
    int ks  = v / npq;
    int nt  = nwh*2 + (e >> 1);
    int oc  = nt*8 + (lane >> 2);
    int ch  = ks*8 + (lane & 3) + (e & 1)*4;
    int nic = Cin >> 6;
    int j  = q / nic;
    int ib = q - j*nic;
    float val = (oc < Cout) ? w[((size_t)oc*Cin + ib*64 + ch)*9 + j] : 0.f;
    float hi = tf32r(val);
    float lo = tf32r(val - hi);
    size_t base = (size_t)q * 2 * per;
    wp[base + r]       = hi;
    wp[base + per + r] = lo;
}

// ---------------- one merged prep kernel (all independent re-layouts) --------
__global__ void __launch_bounds__(256)
k_prep_all(const float* __restrict__ xl, const float* __restrict__ xr,
           float* __restrict__ nhwc,
           const float* __restrict__ dl_w, const float* __restrict__ dr_w,
           float* __restrict__ dlw, float* __restrict__ drw,
           const float* __restrict__ offl_w, const float* __restrict__ offr_w,
           const float* __restrict__ cv_w,
           const float* __restrict__ r11, const float* __restrict__ r12,
           const float* __restrict__ r21, const float* __restrict__ r22,
           float* __restrict__ wp)
{
    __shared__ float tile[32][33];
    int b = blockIdx.x, t = threadIdx.x;
    if (b < 4096){
        const float* in = (b < 2048) ? xl : xr;
        int coloff = (b < 2048) ? 0 : 64;
        int bb = b & 2047;
        int n  = bb >> 10;
        int c0 = ((bb >> 9) & 1) * 32;
        int p0 = (bb & 511) * 32;
        int tx = t & 31, ty = t >> 5;
        const float* src = in + (size_t)n*64*HW;
        float* dst = nhwc + (size_t)n*HW*CSTR;
        #pragma unroll
        for (int i = 0; i < 32; i += 8)
            tile[ty+i][tx] = src[(c0+ty+i)*HW + p0 + tx];
        __syncthreads();
        #pragma unroll
        for (int i = 0; i < 32; i += 8)
            dst[(size_t)(p0+ty+i)*CSTR + coloff + c0 + tx] = tile[tx][ty+i];
    } else if (b < 4240){
        body_prep_dw(dl_w, dlw, (b-4096)*256 + t);
    } else if (b < 4384){
        body_prep_dw(dr_w, drw, (b-4240)*256 + t);
    } else if (b < 4600){
        body_prep_wtc(offl_w, wp + WP_OFFL, 192, 27, 32, (b-4384)*256 + t);
    } else if (b < 4816){
        body_prep_wtc(offr_w, wp + WP_OFFR, 192, 27, 32, (b-4600)*256 + t);
    } else if (b < 5248){
        body_prep_wtc(cv_w,   wp + WP_CV,   192, 64, 64, (b-4816)*256 + t);
    } else if (b < 5392){
        body_prep_wtc(r11,    wp + WP_RB11,  64, 64, 64, (b-5248)*256 + t);
    } else if (b < 5536){
        body_prep_wtc(r12,    wp + WP_RB12,  64, 64, 64, (b-5392)*256 + t);
    } else if (b < 5680){
        body_prep_wtc(r21,    wp + WP_RB21,  64, 64, 64, (b-5536)*256 + t);
    } else {
        body_prep_wtc(r22,    wp + WP_RB22,  64, 64, 64, (b-5680)*256 + t);
    }
}

// ---------------- upsample(2x nearest) + 2x2 conv + pad -> NHWC cols 128-191
__global__ void k_upconv(const float* __restrict__ xd, const float* __restrict__ w,
                         const float* __restrict__ bias, float* __restrict__ out)
{
    __shared__ float4 s_w4[2048];        // 16 oc x 128 ic x 4 taps
    __shared__ float  s_in[9*18];
    int n      = blockIdx.z;
    int ocBase = blockIdx.y * 16;
    int tx0 = (blockIdx.x & 3) * 32;
    int ty0 = (blockIdx.x >> 2) * 16;
    int t  = threadIdx.x;
    int lx = t & 31, ly = t >> 5;

    float* s_w = (float*)s_w4;
    for (int i = t; i < 8192; i += 256) s_w[i] = w[ocBase*512 + i];
    __syncthreads();

    const float* src = xd + (size_t)n*128*4096;
    float accA[16], accB[16];
    #pragma unroll
    for (int oc = 0; oc < 16; oc++){ accA[oc] = 0.f; accB[oc] = 0.f; }

    int X  = tx0 + lx;
    int YA = ty0 + ly, YB = ty0 + ly + 8;
    bool doA = (YA < 127) && (X < 127);
    bool doB = (YB < 127) && (X < 127);
    int x0r = lx >> 1,      x1r = (lx+1) >> 1;
    int yA0 = ly >> 1,      yA1 = (ly+1) >> 1;
    int yB0 = (ly+8) >> 1,  yB1 = (ly+9) >> 1;

    for (int ic = 0; ic < 128; ic++){
        const float* p = src + ic*4096;
        if (t < 162){
            int r = t/18, c = t - r*18;
            int gy = (ty0>>1) + r, gx = (tx0>>1) + c;
            s_in[t] = (gy < 64 && gx < 64) ? p[gy*64 + gx] : 0.f;
        }
        __syncthreads();
        if (doA){
            float v00 = s_in[yA0*18+x0r], v01 = s_in[yA0*18+x1r];
            float v10 = s_in[yA1*18+x0r], v11 = s_in[yA1*18+x1r];
            #pragma unroll
            for (int oc = 0; oc < 16; oc++){
                float4 wv = s_w4[oc*128 + ic];
                accA[oc] += wv.x*v00 + wv.y*v01 + wv.z*v10 + wv.w*v11;
            }
        }
        if (doB){
            float v00 = s_in[yB0*18+x0r], v01 = s_in[yB0*18+x1r];
            float v10 = s_in[yB1*18+x0r], v11 = s_in[yB1*18+x1r];
            #pragma unroll
            for (int oc = 0; oc < 16; oc++){
                float4 wv = s_w4[oc*128 + ic];
                accB[oc] += wv.x*v00 + wv.y*v01 + wv.z*v10 + wv.w*v11;
            }
        }
        __syncthreads();
    }
    float* ob = out + (size_t)n*HW*CSTR;
    #pragma unroll
    for (int oc = 0; oc < 16; oc++){
        int o = ocBase + oc;
        float bv = bias[o];
        ob[(size_t)(YA*128+X)*CSTR + 128 + o] = doA ? (accA[oc] + bv) : 0.f;
        ob[(size_t)(YB*128+X)*CSTR + 128 + o] = doB ? (accB[oc] + bv) : 0.f;
    }
}

// ---------------- mma.sync TF32 implicit-GEMM 3x3 conv ----------------------
// B fragments prepacked float4-contiguous: per ks-iter, NP=64 -> 4 LDG.128,
// NP=32 -> 2 LDG.128 (was 8/4 LDG.64).
template<int NP>
__global__ void __launch_bounds__(256)
k_convMMA(const float* __restrict__ in, int inStride,
          int co0, int co1, int co2, int nicblk,
          const float* __restrict__ wp,
          const float* __restrict__ bias,
          float* __restrict__ out, int outStride, int outCol, int outNCHW, int Cout,
          const float* __restrict__ res, int relu)
{
    constexpr int NT  = NP/16;       // n tiles per warp
    constexpr int NH  = NT/2;        // float4 B loads per half per ks
    constexpr int per = NP*64;       // floats per B half-chunk
    constexpr int A_FLOAT2 = 8*130*4;        // 4160 float2 per buffer
    extern __shared__ char smem[];
    float2* sAh = (float2*)smem;
    float2* sAl = sAh + A_FLOAT2;

    int t = threadIdx.x, lane = t & 31, wrp = t >> 5;
    int mw = wrp & 3, nw = wrp >> 2;
    int g = lane >> 2, tig = lane & 3;
    int y = blockIdx.x, n = blockIdx.z;
    const float* inN = in + (size_t)n*HW*inStride;
    int cos[3] = {co0, co1, co2};

    float d[2][NT][4];
    #pragma unroll
    for (int mt = 0; mt < 2; mt++)
        #pragma unroll
        for (int nt = 0; nt < NT; nt++)
            #pragma unroll
            for (int k = 0; k < 4; k++) d[mt][nt][k] = 0.f;

    for (int ib = 0; ib < nicblk; ib++){
        int co = cos[ib];
        for (int dy = 0; dy < 3; dy++){
            int ys = y + dy - 1;
            bool yv = (unsigned)ys < 128u;
            __syncthreads();                    // prior readers of sA done
            // stage A: 130 px x 8 ks-groups, hi/lo split + pair packing
            for (int i = t; i < 1040; i += 256){
                int ks = i / 130, s = i - ks*130;
                int x = s - 1;
                float4 v0 = make_float4(0.f,0.f,0.f,0.f);
                float4 v1 = make_float4(0.f,0.f,0.f,0.f);
                if (yv && (unsigned)x < 128u){
                    const float* p = inN + (size_t)(ys*128 + x)*inStride + co + ks*8;
                    v0 = *(const float4*)p;
                    v1 = *(const float4*)(p + 4);
                }
                int base = (ks*130 + s)*4;
                float2 h, l;
                h.x = tf32r(v0.x); l.x = tf32r(v0.x - h.x);
                h.y = tf32r(v1.x); l.y = tf32r(v1.x - h.y);
                sAh[base+0] = h; sAl[base+0] = l;
                h.x = tf32r(v0.y); l.x = tf32r(v0.y - h.x);
                h.y = tf32r(v1.y); l.y = tf32r(v1.y - h.y);
                sAh[base+1] = h; sAl[base+1] = l;
                h.x = tf32r(v0.z); l.x = tf32r(v0.z - h.x);
                h.y = tf32r(v1.z); l.y = tf32r(v1.z - h.y);
                sAh[base+2] = h; sAl[base+2] = l;
                h.x = tf32r(v0.w); l.x = tf32r(v0.w - h.x);
                h.y = tf32r(v1.w); l.y = tf32r(v1.w - h.y);
                sAh[base+3] = h; sAl[base+3] = l;
            }
            __syncthreads();                    // sA ready
            for (int dx = 0; dx < 3; dx++){
                int q = (dy*3 + dx)*nicblk + ib;
                const float4* wB4 = (const float4*)(wp + (size_t)q*2*per);
                int s0 = mw*32 + g + dx;
                #pragma unroll
                for (int ks = 0; ks < 8; ks++){
                    float ah[2][4], al[2][4];
                    #pragma unroll
                    for (int mt = 0; mt < 2; mt++){
                        int bi = (ks*130 + s0 + mt*16)*4 + tig;
                        float2 hg  = sAh[bi];
                        float2 hg8 = sAh[bi + 32];
                        float2 lg  = sAl[bi];
                        float2 lg8 = sAl[bi + 32];
                        ah[mt][0] = hg.x;  ah[mt][1] = hg8.x;
                        ah[mt][2] = hg.y;  ah[mt][3] = hg8.y;
                        al[mt][0] = lg.x;  al[mt][1] = lg8.x;
                        al[mt][2] = lg.y;  al[mt][3] = lg8.y;
                    }
                    float2 bh[NT], bl[NT];
                    #pragma unroll
                    for (int h = 0; h < NH; h++){
                        int idx4 = (ks*(NP>>4) + nw*NH + h)*32 + lane;
                        float4 qh = __ldg(wB4 + idx4);
                        float4 ql = __ldg(wB4 + idx4 + per/4);
                        bh[2*h]   = make_float2(qh.x, qh.y);
                        bh[2*h+1] = make_float2(qh.z, qh.w);
                        bl[2*h]   = make_float2(ql.x, ql.y);
                        bl[2*h+1] = make_float2(ql.z, ql.w);
                    }
                    #pragma unroll
                    for (int mt = 0; mt < 2; mt++)
                        #pragma unroll
                        for (int nt = 0; nt < NT; nt++){
                            mma1688(d[mt][nt], ah[mt], bh[nt]);
                            mma1688(d[mt][nt], ah[mt], bl[nt]);
                            mma1688(d[mt][nt], al[mt], bh[nt]);
                        }
                }
            }
        }
    }

    // ---- epilogue ----
    #pragma unroll
    for (int mt = 0; mt < 2; mt++){
        int p0 = y*128 + mw*32 + mt*16 + g;
        int p1 = p0 + 8;
        #pragma unroll
        for (int nt = 0; nt < NT; nt++){
            int oc0 = nw*(NP/2) + nt*8 + 2*tig;
            float v00 = d[mt][nt][0], v01 = d[mt][nt][1];
            float v10 = d[mt][nt][2], v11 = d[mt][nt][3];
            float b0v = (oc0   < Cout) ? bias[oc0]   : 0.f;
            float b1v = (oc0+1 < Cout) ? bias[oc0+1] : 0.f;
            v00 += b0v; v01 += b1v; v10 += b0v; v11 += b1v;
            if (res){
                v00 += res[((size_t)n*HW + p0)*64 + oc0];
                v01 += res[((size_t)n*HW + p0)*64 + oc0 + 1];
                v10 += res[((size_t)n*HW + p1)*64 + oc0];
                v11 += res[((size_t)n*HW + p1)*64 + oc0 + 1];
            }
            if (relu){
                v00 = fmaxf(v00, 0.f); v01 = fmaxf(v01, 0.f);
                v10 = fmaxf(v10, 0.f); v11 = fmaxf(v11, 0.f);
            }
            if (outNCHW){
                if (oc0 < Cout){
                    out[((size_t)n*Cout + oc0)*HW + p0] = v00;
                    out[((size_t)n*Cout + oc0)*HW + p1] = v10;
                }
                if (oc0 + 1 < Cout){
                    out[((size_t)n*Cout + oc0+1)*HW + p0] = v01;
                    out[((size_t)n*Cout + oc0+1)*HW + p1] = v11;
                }
            } else {
                float* o0 = out + ((size_t)n*HW + p0)*outStride + outCol;
                float* o1 = out + ((size_t)n*HW + p1)*outStride + outCol;
                if (oc0 + 1 < Cout){
                    *(float2*)(o0 + oc0) = make_float2(v00, v01);
                    *(float2*)(o1 + oc0) = make_float2(v10, v11);
                } else if (oc0 < Cout){
                    o0[oc0] = v00; o1[oc0] = v10;
                }
            }
        }
    }
}

// ---------------- modulated deformable 3x3 conv (mma GEMM) -------------------
#define PXS 580
__global__ void k_deform(const float* __restrict__ nhwc, int xco,
                         const float* __restrict__ off,
                         const float* __restrict__ dwp, const float* __restrict__ bias,
                         float* __restrict__ out, int oco)
{
    extern __shared__ char smem[];
    float* smf = (float*)smem;
    float* s_samp = smf;                  // 16 * 580 floats
    float* s_w00  = smf + 16*PXS;
    float* s_w01  = s_w00 + 144;
    float* s_w10  = s_w01 + 144;
    float* s_w11  = s_w10 + 144;
    int*   s_o00  = (int*)(s_w11 + 144);
    int*   s_o01  = s_o00 + 144;
    int*   s_o10  = s_o01 + 144;
    int*   s_o11  = s_o10 + 144;

    int n  = blockIdx.z;
    int y0 = blockIdx.y * 2;
    int x0 = blockIdx.x * 8;
    int t  = threadIdx.x;

    if (t < 144){
        int p = t / 9, k = t - p*9;
        int yy = y0 + (p >> 3), xx = x0 + (p & 7);
        const float* ob = off + ((size_t)n*HW + yy*128 + xx)*32;
        float dyv = ob[2*k];
        float dxv = ob[2*k+1];
        float mv  = 1.f / (1.f + __expf(-ob[18+k]));
        float py = dyv + (float)(k/3) - 1.f + (float)yy;
        float px = dxv + (float)(k%3) - 1.f + (float)xx;
        float fy = floorf(py), fx = floorf(px);
        int iy0 = (int)fy, ix0 = (int)fx;
        float wy = py - fy, wx = px - fx;
        int iy1 = iy0 + 1, ix1 = ix0 + 1;
        bool y0v = (unsigned)iy0 < 128u, y1v = (unsigned)iy1 < 128u;
        bool x0v = (unsigned)ix0 < 128u, x1v = (unsigned)ix1 < 128u;
        s_o00[t] = (y0v && x0v) ? (iy0*128 + ix0)*160 : -1;
        s_o01[t] = (y0v && x1v) ? (iy0*128 + ix1)*160 : -1;
        s_o10[t] = (y1v && x0v) ? (iy1*128 + ix0)*160 : -1;
        s_o11[t] = (y1v && x1v) ? (iy1*128 + ix1)*160 : -1;
        s_w00[t] = mv*(1.f-wy)*(1.f-wx);
        s_w01[t] = mv*(1.f-wy)*wx;
        s_w10[t] = mv*wy*(1.f-wx);
        s_w11[t] = mv*wy*wx;
    }
    __syncthreads();

    int lane = t & 31, wrp = t >> 5;
    int g = lane >> 2, tig = lane & 3;
    const float2* xb = (const float2*)(nhwc + (size_t)n*HW*CSTR + xco);  // idx: pix*160 + lane
    float2* s_samp2 = (float2*)s_samp;    // px stride PXS/2 = 290 float2
    for (int pp = wrp; pp < 16; pp += 8){
        #pragma unroll
        for (int k = 0; k < 9; k++){
            int pk = pp*9 + k;
            int o00 = s_o00[pk], o01 = s_o01[pk], o10 = s_o10[pk], o11 = s_o11[pk];
            float w00 = s_w00[pk], w01 = s_w01[pk], w10 = s_w10[pk], w11 = s_w11[pk];
            float ax = 0.f, ay = 0.f;
            if (o00 >= 0){ float2 v = xb[o00 + lane]; ax = fmaf(w00, v.x, ax); ay = fmaf(w00, v.y, ay); }
            if (o01 >= 0){ float2 v = xb[o01 + lane]; ax = fmaf(w01, v.x, ax); ay = fmaf(w01, v.y, ay); }
            if (o10 >= 0){ float2 v = xb[o10 + lane]; ax = fmaf(w10, v.x, ax); ay = fmaf(w10, v.y, ay); }
            if (o11 >= 0){ float2 v = xb[o11 + lane]; ax = fmaf(w11, v.x, ax); ay = fmaf(w11, v.y, ay); }
            s_samp2[pp*290 + k*32 + lane] = make_float2(ax, ay);
        }
    }
    __syncthreads();

    // GEMM 16x64x576: warp wrp -> oc slice [8*wrp, 8*wrp+8)
    float d[4] = {0.f, 0.f, 0.f, 0.f};
    const float2* wb = (const float2*)dwp;           // hi: 18432 float2, lo: +18432
    const float* pg  = s_samp + g*PXS;
    const float* pg8 = s_samp + (g+8)*PXS;
    #pragma unroll 4
    for (int ks = 0; ks < 72; ks++){
        int c0 = ks*8 + tig;
        float a0 = pg [c0],     a1 = pg8[c0];
        float a2 = pg [c0 + 4], a3 = pg8[c0 + 4];
        float ah[4], al[4];
        ah[0] = tf32r(a0); al[0] = tf32r(a0 - ah[0]);
        ah[1] = tf32r(a1); al[1] = tf32r(a1 - ah[1]);
        ah[2] = tf32r(a2); al[2] = tf32r(a2 - ah[2]);
        ah[3] = tf32r(a3); al[3] = tf32r(a3 - ah[3]);
        int bidx = (ks*8 + wrp)*32 + lane;
        float2 bh = __ldg(wb + bidx);
        float2 bl = __ldg(wb + 18432 + bidx);
        mma1688(d, ah, bh);
        mma1688(d, ah, bl);
        mma1688(d, al, bh);
    }

    // epilogue
    int oc0 = 8*wrp + 2*tig;
    float b0 = bias[oc0], b1 = bias[oc0+1];
    {
        int px = g;
        int yy = y0 + (px >> 3), xx = x0 + (px & 7);
        float* op = out + ((size_t)n*HW + yy*128 + xx)*CSTR + oco + oc0;
        *(float2*)op = make_float2(d[0] + b0, d[1] + b1);
    }
    {
        int px = g + 8;
        int yy = y0 + (px >> 3), xx = x0 + (px & 7);
        float* op = out + ((size_t)n*HW + yy*128 + xx)*CSTR + oco + oc0;
        *(float2*)op = make_float2(d[2] + b0, d[3] + b1);
    }
}

// ---------------------------------------------------------------------------
extern "C" void kernel_launch(void* const* d_in, const int* in_sizes, int n_in,
                              void* d_out, int out_size)
{
    const float* xd     = (const float*)d_in[0];
    const float* xl     = (const float*)d_in[1];
    const float* xr     = (const float*)d_in[2];
    const float* up_w   = (const float*)d_in[3];
    const float* up_b   = (const float*)d_in[4];
    const float* offl_w = (const float*)d_in[5];
    const float* offl_b = (const float*)d_in[6];
    const float* dl_w   = (const float*)d_in[7];
    const float* dl_b   = (const float*)d_in[8];
    const float* offr_w = (const float*)d_in[9];
    const float* offr_b = (const float*)d_in[10];
    const float* dr_w   = (const float*)d_in[11];
    const float* dr_b   = (const float*)d_in[12];
    const float* cv_w   = (const float*)d_in[13];
    const float* cv_b   = (const float*)d_in[14];

    const float *rb1_w1, *rb1_b1, *rb1_w2, *rb1_b2;
    const float *rb2_w1, *rb2_b1, *rb2_w2, *rb2_b2;
    if (in_sizes[16] == 64){
        rb1_w1 = (const float*)d_in[15]; rb1_b1 = (const float*)d_in[16];
        rb1_w2 = (const float*)d_in[17]; rb1_b2 = (const float*)d_in[18];
        rb2_w1 = (const float*)d_in[19]; rb2_b1 = (const float*)d_in[20];
        rb2_w2 = (const float*)d_in[21]; rb2_b2 = (const float*)d_in[22];
    } else {
        rb1_w1 = (const float*)d_in[15]; rb1_w2 = (const float*)d_in[16];
        rb2_w1 = (const float*)d_in[17]; rb2_w2 = (const float*)d_in[18];
        rb1_b1 = (const float*)d_in[19]; rb1_b2 = (const float*)d_in[20];
        rb2_b1 = (const float*)d_in[21]; rb2_b2 = (const float*)d_in[22];
    }

    float *p_nhwc, *p_off, *p_x0, *p_tmp, *p_x1, *p_dlw, *p_drw, *p_wp;
    cudaGetSymbolAddress((void**)&p_nhwc, g_nhwc);
    cudaGetSymbolAddress((void**)&p_off,  g_offb);
    cudaGetSymbolAddress((void**)&p_x0,   g_x0);
    cudaGetSymbolAddress((void**)&p_tmp,  g_tmp);
    cudaGetSymbolAddress((void**)&p_x1,   g_x1);
    cudaGetSymbolAddress((void**)&p_dlw,  g_dlw);
    cudaGetSymbolAddress((void**)&p_drw,  g_drw);
    cudaGetSymbolAddress((void**)&p_wp,   g_wp);

    // conv smem: A hi/lo only = 2*33280 = 66560 (3 blocks/SM)
    const int SMC = 66560;
    cudaFuncSetAttribute(k_convMMA<64>, cudaFuncAttributeMaxDynamicSharedMemorySize, SMC);
    cudaFuncSetAttribute(k_convMMA<32>, cudaFuncAttributeMaxDynamicSharedMemorySize, SMC);
    const int SMD = (16*PXS + 8*144)*4 + 64;   // ~41.8KB

    // 0: dummy (ncu -s5 -c1 then captures launch #6 = right offset conv)
    k_nop<<<1, 32>>>();
    // 1: all independent prep work in one launch
    k_prep_all<<<5824, 256>>>(xl, xr, p_nhwc, dl_w, dr_w, p_dlw, p_drw,
                              offl_w, offr_w, cv_w, rb1_w1, rb1_w2, rb2_w1, rb2_w2, p_wp);
    // 2: upsample-conv -> NHWC cols 128-191
    k_upconv<<<dim3(32, 4, 2), 256>>>(xd, up_w, up_b, p_nhwc);

    dim3 cg(128, 1, 2);
    // 3: left offset conv (192->27) on [xl|xr|xd]
    k_convMMA<32><<<cg, 256, SMC>>>(p_nhwc, CSTR, 0, 64, 128, 3, p_wp + WP_OFFL,
                                    offl_b, p_off, 32, 0, 0, 27, nullptr, 0);
    // 4: deform xl -> cols 192
    k_deform<<<dim3(16, 64, 2), 256, SMD>>>(p_nhwc, 0,   p_off, p_dlw, dl_b, p_nhwc, 192);
    // 5: right offset conv on [xl2|xr|xd]  (captured by ncu)
    k_convMMA<32><<<cg, 256, SMC>>>(p_nhwc, CSTR, 192, 64, 128, 3, p_wp + WP_OFFR,
                                    offr_b, p_off, 32, 0, 0, 27, nullptr, 0);
    // 6: deform xr -> cols 256
    k_deform<<<dim3(16, 64, 2), 256, SMD>>>(p_nhwc, 64,  p_off, p_drw, dr_b, p_nhwc, 256);
    // 7: fuse conv (192->64) + ReLU on [xl2|xr2|xd] -> x0 (NHWC64)
    k_convMMA<64><<<cg, 256, SMC>>>(p_nhwc, CSTR, 192, 256, 128, 3, p_wp + WP_CV,
                                    cv_b, p_x0, 64, 0, 0, 64, nullptr, 1);
    // 8-9: residual block 1
    k_convMMA<64><<<cg, 256, SMC>>>(p_x0,  64, 0, 0, 0, 1, p_wp + WP_RB11,
                                    rb1_b1, p_tmp, 64, 0, 0, 64, nullptr, 1);
    k_convMMA<64><<<cg, 256, SMC>>>(p_tmp, 64, 0, 0, 0, 1, p_wp + WP_RB12,
                                    rb1_b2, p_x1, 64, 0, 0, 64, p_x0, 0);
    // 10-11: residual block 2 (final conv writes NCHW straight to d_out)
    k_convMMA<64><<<cg, 256, SMC>>>(p_x1,  64, 0, 0, 0, 1, p_wp + WP_RB21,
                                    rb2_b1, p_tmp, 64, 0, 0, 64, nullptr, 1);
    k_convMMA<64><<<cg, 256, SMC>>>(p_tmp, 64, 0, 0, 0, 1, p_wp + WP_RB22,
                                    rb2_b2, (float*)d_out, 64, 0, 1, 64, p_x1, 0);
}